// round 10
// baseline (speedup 1.0000x reference)
#include <cuda_runtime.h>

#define NR    8192
#define NQ    4096
#define KNN_K 16
#define C4    64           // 256 channels / 4 (float4)

#define QPW             2
#define WARPS_PER_BLOCK 14
#define KNN_THREADS     (WARPS_PER_BLOCK * 32)   // 448
#define WARP_PAIRS      (NQ / QPW)               // 2048
#define KNN_BLOCKS      ((WARP_PAIRS + WARPS_PER_BLOCK - 1) / WARPS_PER_BLOCK) // 147
#define SAMPLE_ITERS    64         // phase-1 samples 32*64 = 2048 refs
#define FULL_ITERS      (NR / 32)  // 256
#define BUF_CAP         256
#define TAU_SLACK       1e-3f      // >> max |d - (q2 + t)| rounding error (~2e-5)

typedef unsigned long long ull;

__device__ int g_knn_idx[NQ * KNN_K];

// q2/r2: jnp.sum(x*x) = sequential add of rn squares (no FMA).
__device__ __forceinline__ float sq3(float x, float y, float z) {
    return __fadd_rn(__fadd_rn(__fmul_rn(x, x), __fmul_rn(y, y)), __fmul_rn(z, z));
}
// cross: XLA dot accumulation = fmuladd chain (seed = rn product).
__device__ __forceinline__ float dot3_fma(float ax, float ay, float az,
                                          float bx, float by, float bz) {
    return __fmaf_rn(az, bz, __fmaf_rn(ay, by, __fmul_rn(ax, bx)));
}
// Lexicographic (dist, idx) as one sortable u64 (survivor buffer only).
__device__ __forceinline__ ull make_key(float d, int r) {
    unsigned b = __float_as_uint(d);
    b ^= ((unsigned)((int)b >> 31)) | 0x80000000u;
    return ((ull)b << 32) | (unsigned)r;
}

// Float-only bitonic sort of 32 lane values; returns 16th smallest.
__device__ __forceinline__ float warp_16th(float sd, int lane) {
#pragma unroll
    for (int kk = 2; kk <= 32; kk <<= 1) {
#pragma unroll
        for (int j = kk >> 1; j > 0; j >>= 1) {
            const float o = __shfl_xor_sync(0xffffffffu, sd, j);
            const bool keepMin = (((lane & j) == 0) == ((lane & kk) == 0));
            sd = keepMin ? fminf(sd, o) : fmaxf(sd, o);
        }
    }
    return __shfl_sync(0xffffffffu, sd, KNN_K - 1);
}

// Extract 16 smallest keys from wbuf[0..cnt) into g_knn_idx for query q.
__device__ __forceinline__ void select16(ull* wbuf, int cnt, int q, int lane) {
    for (int sel = 0; sel < KNN_K; ++sel) {
        ull best = ~0ull;
        int bpos = -1;
        for (int i = lane; i < cnt; i += 32) {
            const ull v = wbuf[i];
            if (v < best) { best = v; bpos = i; }
        }
#pragma unroll
        for (int off = 16; off > 0; off >>= 1) {
            const ull ob = __shfl_down_sync(0xffffffffu, best, off);
            const int op = __shfl_down_sync(0xffffffffu, bpos, off);
            if (ob < best) { best = ob; bpos = op; }
        }
        bpos = __shfl_sync(0xffffffffu, bpos, 0);
        if (lane == 0) g_knn_idx[q * KNN_K + sel] = (int)(wbuf[bpos] & 0xffffffffu);
        if (lane == (bpos & 31)) wbuf[bpos] = ~0ull;
        __syncwarp();
    }
}

// One warp per TWO queries, batch-4 ref loads: each float4 LDS feeds both
// queries (halves LDS bytes/pair); 4 independent loads + 8 independent FMA
// chains per warp-iter hide LDS latency at 14 warps/SM.
__global__ void __launch_bounds__(KNN_THREADS, 1) knn_kernel(
        const float* __restrict__ xyz_prev,
        const float* __restrict__ xyz_cur) {
    extern __shared__ unsigned char smraw[];
    float4* sref = (float4*)smraw;                          // 128 KB
    ull*    bufs = (ull*)(smraw + NR * sizeof(float4));     // 14*2*256*8 = 56 KB

    const int tid = threadIdx.x;
    for (int i = tid; i < NR; i += KNN_THREADS) {
        float x = xyz_prev[3 * i + 0];
        float y = xyz_prev[3 * i + 1];
        float z = xyz_prev[3 * i + 2];
        sref[i] = make_float4(x, y, z, sq3(x, y, z));
    }
    __syncthreads();

    const int warp = tid >> 5;
    const int lane = tid & 31;
    const int wp = blockIdx.x * WARPS_PER_BLOCK + warp;
    if (wp >= WARP_PAIRS) return;           // whole warp exits together
    const int q0 = wp * QPW, q1 = q0 + 1;
    ull* wbuf0 = bufs + warp * (QPW * BUF_CAP);
    ull* wbuf1 = wbuf0 + BUF_CAP;

    const float ax = xyz_cur[3 * q0 + 0], ay = xyz_cur[3 * q0 + 1], az = xyz_cur[3 * q0 + 2];
    const float bx = xyz_cur[3 * q1 + 0], by = xyz_cur[3 * q1 + 1], bz = xyz_cur[3 * q1 + 2];
    const float a2 = sq3(ax, ay, az);
    const float b2 = sq3(bx, by, bz);

    // ---- Phase 1: per-lane min of shifted dist t = r2 - 2*cross (index-free) ----
    const float INF = __int_as_float(0x7f800000);
    float ma0 = INF, ma1 = INF, ma2 = INF, ma3 = INF;
    float mb0 = INF, mb1 = INF, mb2 = INF, mb3 = INF;
    for (int i = 0; i < SAMPLE_ITERS; i += 4) {
        const float4 p0 = sref[lane + 32 * (i + 0)];
        const float4 p1 = sref[lane + 32 * (i + 1)];
        const float4 p2 = sref[lane + 32 * (i + 2)];
        const float4 p3 = sref[lane + 32 * (i + 3)];
        ma0 = fminf(ma0, __fmaf_rn(-2.0f, dot3_fma(ax, ay, az, p0.x, p0.y, p0.z), p0.w));
        ma1 = fminf(ma1, __fmaf_rn(-2.0f, dot3_fma(ax, ay, az, p1.x, p1.y, p1.z), p1.w));
        ma2 = fminf(ma2, __fmaf_rn(-2.0f, dot3_fma(ax, ay, az, p2.x, p2.y, p2.z), p2.w));
        ma3 = fminf(ma3, __fmaf_rn(-2.0f, dot3_fma(ax, ay, az, p3.x, p3.y, p3.z), p3.w));
        mb0 = fminf(mb0, __fmaf_rn(-2.0f, dot3_fma(bx, by, bz, p0.x, p0.y, p0.z), p0.w));
        mb1 = fminf(mb1, __fmaf_rn(-2.0f, dot3_fma(bx, by, bz, p1.x, p1.y, p1.z), p1.w));
        mb2 = fminf(mb2, __fmaf_rn(-2.0f, dot3_fma(bx, by, bz, p2.x, p2.y, p2.z), p2.w));
        mb3 = fminf(mb3, __fmaf_rn(-2.0f, dot3_fma(bx, by, bz, p3.x, p3.y, p3.z), p3.w));
    }
    const float tau_a = warp_16th(fminf(fminf(ma0, ma1), fminf(ma2, ma3)), lane) + TAU_SLACK;
    const float tau_b = warp_16th(fminf(fminf(mb0, mb1), fminf(mb2, mb3)), lane) + TAU_SLACK;

    // ---- Phase 2: full scan; survivors t <= tau (superset of exact top-16) ----
    int base_a = 0, base_b = 0;
    const unsigned lt_mask = (1u << lane) - 1u;
    for (int i = 0; i < FULL_ITERS; i += 4) {
        const float4 p0 = sref[lane + 32 * (i + 0)];
        const float4 p1 = sref[lane + 32 * (i + 1)];
        const float4 p2 = sref[lane + 32 * (i + 2)];
        const float4 p3 = sref[lane + 32 * (i + 3)];
        const float ca0 = dot3_fma(ax, ay, az, p0.x, p0.y, p0.z);
        const float ca1 = dot3_fma(ax, ay, az, p1.x, p1.y, p1.z);
        const float ca2 = dot3_fma(ax, ay, az, p2.x, p2.y, p2.z);
        const float ca3 = dot3_fma(ax, ay, az, p3.x, p3.y, p3.z);
        const float cb0 = dot3_fma(bx, by, bz, p0.x, p0.y, p0.z);
        const float cb1 = dot3_fma(bx, by, bz, p1.x, p1.y, p1.z);
        const float cb2 = dot3_fma(bx, by, bz, p2.x, p2.y, p2.z);
        const float cb3 = dot3_fma(bx, by, bz, p3.x, p3.y, p3.z);
        const float ta0 = __fmaf_rn(-2.0f, ca0, p0.w);
        const float ta1 = __fmaf_rn(-2.0f, ca1, p1.w);
        const float ta2 = __fmaf_rn(-2.0f, ca2, p2.w);
        const float ta3 = __fmaf_rn(-2.0f, ca3, p3.w);
        const float tb0 = __fmaf_rn(-2.0f, cb0, p0.w);
        const float tb1 = __fmaf_rn(-2.0f, cb1, p1.w);
        const float tb2 = __fmaf_rn(-2.0f, cb2, p2.w);
        const float tb3 = __fmaf_rn(-2.0f, cb3, p3.w);

#pragma unroll
        for (int j = 0; j < 4; ++j) {
            const float ta = (j == 0) ? ta0 : (j == 1) ? ta1 : (j == 2) ? ta2 : ta3;
            const float tb = (j == 0) ? tb0 : (j == 1) ? tb1 : (j == 2) ? tb2 : tb3;
            const float ca = (j == 0) ? ca0 : (j == 1) ? ca1 : (j == 2) ? ca2 : ca3;
            const float cb = (j == 0) ? cb0 : (j == 1) ? cb1 : (j == 2) ? cb2 : cb3;
            const float pw = (j == 0) ? p0.w : (j == 1) ? p1.w : (j == 2) ? p2.w : p3.w;
            const int r = lane + 32 * (i + j);

            const bool pa = (ta <= tau_a);
            const bool pb = (tb <= tau_b);
            const unsigned mA = __ballot_sync(0xffffffffu, pa);
            const unsigned mB = __ballot_sync(0xffffffffu, pb);
            if (pa) {
                const float d = __fmaf_rn(-2.0f, ca, __fadd_rn(a2, pw));
                const int pos = base_a + __popc(mA & lt_mask);
                if (pos < BUF_CAP) wbuf0[pos] = make_key(d, r);
            }
            if (pb) {
                const float d = __fmaf_rn(-2.0f, cb, __fadd_rn(b2, pw));
                const int pos = base_b + __popc(mB & lt_mask);
                if (pos < BUF_CAP) wbuf1[pos] = make_key(d, r);
            }
            base_a += __popc(mA);
            base_b += __popc(mB);
        }
    }
    __syncwarp();

    // ---- Phase 3: exact selection per query ----
    select16(wbuf0, (base_a < BUF_CAP) ? base_a : BUF_CAP, q0, lane);
    select16(wbuf1, (base_b < BUF_CAP) ? base_b : BUF_CAP, q1, lane);
}

// One block per query. blockDim = (64, 4). Thread y owns neighbors 4y..4y+3:
// one int4 idx load -> 4 independent gathers (MLP=4), cur reused from regs.
__global__ void __launch_bounds__(256) gather_kernel(
        const float4* __restrict__ feat_prev,
        const float4* __restrict__ feat_cur,
        float4* __restrict__ out) {
    const int q  = blockIdx.x;
    const int c4 = threadIdx.x;   // 0..63
    const int y  = threadIdx.y;   // 0..3

    const float4 cur = feat_cur[q * C4 + c4];
    const int4 iv = __ldg((const int4*)(g_knn_idx + q * KNN_K + 4 * y));

    const float4 p0 = feat_prev[iv.x * C4 + c4];
    const float4 p1 = feat_prev[iv.y * C4 + c4];
    const float4 p2 = feat_prev[iv.z * C4 + c4];
    const float4 p3 = feat_prev[iv.w * C4 + c4];

    const int row0 = q * KNN_K + 4 * y;
#pragma unroll
    for (int jj = 0; jj < 4; ++jj) {
        const float4 p = (jj == 0) ? p0 : (jj == 1) ? p1 : (jj == 2) ? p2 : p3;
        float4 dv;
        dv.x = p.x - cur.x; dv.y = p.y - cur.y;
        dv.z = p.z - cur.z; dv.w = p.w - cur.w;
        const long long row = row0 + jj;
        __stcs(&out[row * 128 + c4], dv);
        __stcs(&out[row * 128 + C4 + c4], cur);
    }
}

extern "C" void kernel_launch(void* const* d_in, const int* in_sizes, int n_in,
                              void* d_out, int out_size) {
    const float*  xyz_prev  = (const float*)d_in[0];
    const float*  xyz_cur   = (const float*)d_in[1];
    const float4* feat_prev = (const float4*)d_in[2];
    const float4* feat_cur  = (const float4*)d_in[3];
    float4* out = (float4*)d_out;

    (void)in_sizes; (void)n_in; (void)out_size;

    const int smem = NR * sizeof(float4) + WARPS_PER_BLOCK * QPW * BUF_CAP * sizeof(ull);
    cudaFuncSetAttribute(knn_kernel, cudaFuncAttributeMaxDynamicSharedMemorySize, smem);

    knn_kernel<<<KNN_BLOCKS, KNN_THREADS, smem>>>(xyz_prev, xyz_cur);
    gather_kernel<<<NQ, dim3(64, 4)>>>(feat_prev, feat_cur, out);
}

// round 11
// speedup vs baseline: 1.2631x; 1.2631x over previous
#include <cuda_runtime.h>

#define NR    8192
#define NQ    4096
#define KNN_K 16
#define C4    64            // 256 channels / 4 (float4)

#define G     16            // grid cells per dim
#define G3    (G * G * G)
#define GLO   (-3.3f)
#define GH    (0.4125f)     // G*GH covers [-3.3, 3.3]; outliers clamp to edge cells
#define INV_GH (1.0f / GH)

#define NSAMP        2048
#define SAMPLE_ITERS (NSAMP / 32)   // 64
#define WPB          28
#define KNN_THREADS  (WPB * 32)     // 896
#define KNN_BLOCKS   ((NQ + WPB - 1) / WPB)   // 147
#define BUF_CAP      256
#define SLACK        1e-3f          // >> all rounding gaps (~1e-5) in play

typedef unsigned long long ull;

__device__ int    g_knn_idx[NQ * KNN_K];
__device__ float4 g_sorted[NR];       // cell-sorted refs: (x,y,z, idx-bits)
__device__ float4 g_sample[NSAMP];    // spatially-unbiased sample: (x,y,z, r2)
__device__ int    g_cell_start[G3 + 1];

// q2/r2: jnp.sum(x*x) = sequential add of rn squares (no FMA).
__device__ __forceinline__ float sq3(float x, float y, float z) {
    return __fadd_rn(__fadd_rn(__fmul_rn(x, x), __fmul_rn(y, y)), __fmul_rn(z, z));
}
// cross: XLA dot accumulation = fmuladd chain (seed = rn product).
__device__ __forceinline__ float dot3_fma(float ax, float ay, float az,
                                          float bx, float by, float bz) {
    return __fmaf_rn(az, bz, __fmaf_rn(ay, by, __fmul_rn(ax, bx)));
}
// Lexicographic (dist, idx) as one sortable u64 (survivor buffer only).
__device__ __forceinline__ ull make_key(float d, int r) {
    unsigned b = __float_as_uint(d);
    b ^= ((unsigned)((int)b >> 31)) | 0x80000000u;
    return ((ull)b << 32) | (unsigned)r;
}
__device__ __forceinline__ int cell_of(float v) {
    int c = (int)floorf((v - GLO) * INV_GH);
    return min(G - 1, max(0, c));
}

// Single block: histogram -> prefix -> scatter refs cell-sorted; build sample pack.
__global__ void bin_kernel(const float* __restrict__ xyz_prev) {
    __shared__ int cnt[G3];
    __shared__ int partial[1024];
    const int tid = threadIdx.x;

    for (int c = tid; c < G3; c += 1024) cnt[c] = 0;
    __syncthreads();

    for (int r = tid; r < NR; r += 1024) {
        const float x = xyz_prev[3 * r + 0];
        const float y = xyz_prev[3 * r + 1];
        const float z = xyz_prev[3 * r + 2];
        const int cid = (cell_of(z) * G + cell_of(y)) * G + cell_of(x);
        atomicAdd(&cnt[cid], 1);
    }
    __syncthreads();

    // blocked exclusive scan: thread owns 4 cells
    const int c0 = tid * 4;
    const int l0 = cnt[c0], l1 = cnt[c0 + 1], l2 = cnt[c0 + 2], l3 = cnt[c0 + 3];
    const int s = l0 + l1 + l2 + l3;
    partial[tid] = s;
    __syncthreads();
    for (int off = 1; off < 1024; off <<= 1) {
        const int v = (tid >= off) ? partial[tid - off] : 0;
        __syncthreads();
        partial[tid] += v;
        __syncthreads();
    }
    int run = partial[tid] - s;            // exclusive prefix
    g_cell_start[c0] = run;     cnt[c0] = run;     run += l0;
    g_cell_start[c0 + 1] = run; cnt[c0 + 1] = run; run += l1;
    g_cell_start[c0 + 2] = run; cnt[c0 + 2] = run; run += l2;
    g_cell_start[c0 + 3] = run; cnt[c0 + 3] = run; run += l3;
    if (tid == 1023) g_cell_start[G3] = NR;
    __syncthreads();

    // scatter (within-cell order nondeterministic -> harmless: selection uses total-order keys)
    for (int r = tid; r < NR; r += 1024) {
        const float x = xyz_prev[3 * r + 0];
        const float y = xyz_prev[3 * r + 1];
        const float z = xyz_prev[3 * r + 2];
        const int cid = (cell_of(z) * G + cell_of(y)) * G + cell_of(x);
        const int pos = atomicAdd(&cnt[cid], 1);
        g_sorted[pos] = make_float4(x, y, z, __int_as_float(r));
    }
    // sample pack: every 4th ref in original (random) order, r2 precomputed
    for (int i = tid; i < NSAMP; i += 1024) {
        const int r = 4 * i;
        const float x = xyz_prev[3 * r + 0];
        const float y = xyz_prev[3 * r + 1];
        const float z = xyz_prev[3 * r + 2];
        g_sample[i] = make_float4(x, y, z, sq3(x, y, z));
    }
}

// Float-only bitonic sort of 32 lane values; returns 16th smallest.
__device__ __forceinline__ float warp_16th(float sd, int lane) {
#pragma unroll
    for (int kk = 2; kk <= 32; kk <<= 1) {
#pragma unroll
        for (int j = kk >> 1; j > 0; j >>= 1) {
            const float o = __shfl_xor_sync(0xffffffffu, sd, j);
            const bool keepMin = (((lane & j) == 0) == ((lane & kk) == 0));
            sd = keepMin ? fminf(sd, o) : fmaxf(sd, o);
        }
    }
    return __shfl_sync(0xffffffffu, sd, KNN_K - 1);
}

// One warp per query: sample -> tau -> scan only cells intersecting the tau-ball.
__global__ void __launch_bounds__(KNN_THREADS, 1) knn_kernel(
        const float* __restrict__ xyz_cur) {
    extern __shared__ ull bufs[];     // WPB * BUF_CAP keys

    const int warp = threadIdx.x >> 5;
    const int lane = threadIdx.x & 31;
    const int q = blockIdx.x * WPB + warp;
    if (q >= NQ) return;              // per-warp exit; no block sync anywhere
    ull* wbuf = bufs + warp * BUF_CAP;

    const float qx = xyz_cur[3 * q + 0];
    const float qy = xyz_cur[3 * q + 1];
    const float qz = xyz_cur[3 * q + 2];
    const float q2 = sq3(qx, qy, qz);

    // ---- Phase 1: tau from 2048-point sample (shifted t = r2 - 2*cross) ----
    const float INF = __int_as_float(0x7f800000);
    float m0 = INF, m1 = INF, m2 = INF, m3 = INF;
    for (int i = 0; i < SAMPLE_ITERS; i += 4) {
        const float4 p0 = __ldg(&g_sample[lane + 32 * (i + 0)]);
        const float4 p1 = __ldg(&g_sample[lane + 32 * (i + 1)]);
        const float4 p2 = __ldg(&g_sample[lane + 32 * (i + 2)]);
        const float4 p3 = __ldg(&g_sample[lane + 32 * (i + 3)]);
        m0 = fminf(m0, __fmaf_rn(-2.0f, dot3_fma(qx, qy, qz, p0.x, p0.y, p0.z), p0.w));
        m1 = fminf(m1, __fmaf_rn(-2.0f, dot3_fma(qx, qy, qz, p1.x, p1.y, p1.z), p1.w));
        m2 = fminf(m2, __fmaf_rn(-2.0f, dot3_fma(qx, qy, qz, p2.x, p2.y, p2.z), p2.w));
        m3 = fminf(m3, __fmaf_rn(-2.0f, dot3_fma(qx, qy, qz, p3.x, p3.y, p3.z), p3.w));
    }
    const float tau_t = warp_16th(fminf(fminf(m0, m1), fminf(m2, m3)), lane);
    // valid d-space threshold (>= true d16), plus slack for t<->d rounding
    const float R2 = fmaxf(tau_t + q2 + SLACK, 0.0f) + SLACK;
    const float R  = sqrtf(R2);

    const int cxlo = cell_of(qx - R), cxhi = cell_of(qx + R);
    const int cylo = cell_of(qy - R), cyhi = cell_of(qy + R);
    const int czlo = cell_of(qz - R), czhi = cell_of(qz + R);

    // ---- Phase 2: scan candidate cell rows, compact survivors d <= R2 ----
    int base = 0;
    const unsigned lt_mask = (1u << lane) - 1u;
    for (int cz = czlo; cz <= czhi; ++cz) {
        for (int cy = cylo; cy <= cyhi; ++cy) {
            const int row = (cz * G + cy) * G;
            const int s = __ldg(&g_cell_start[row + cxlo]);
            const int e = __ldg(&g_cell_start[row + cxhi + 1]);
            for (int b = s; b < e; b += 32) {
                const int i = b + lane;
                const bool valid = (i < e);
                const float4 p = __ldg(&g_sorted[valid ? i : (NR - 1)]);
                const float r2 = sq3(p.x, p.y, p.z);
                const float cr = dot3_fma(qx, qy, qz, p.x, p.y, p.z);
                const float d  = __fmaf_rn(-2.0f, cr, __fadd_rn(q2, r2));
                const bool pred = valid && (d <= R2);
                const unsigned m = __ballot_sync(0xffffffffu, pred);
                if (pred) {
                    const int pos = base + __popc(m & lt_mask);
                    if (pos < BUF_CAP) wbuf[pos] = make_key(d, __float_as_int(p.w));
                }
                base += __popc(m);
            }
        }
    }
    const int cnt = (base < BUF_CAP) ? base : BUF_CAP;   // >= 16 guaranteed
    __syncwarp();

    // ---- Phase 3: 16 argmin-extract rounds over the survivor buffer ----
    for (int sel = 0; sel < KNN_K; ++sel) {
        ull best = ~0ull;
        int bpos = -1;
        for (int i = lane; i < cnt; i += 32) {
            const ull v = wbuf[i];
            if (v < best) { best = v; bpos = i; }
        }
#pragma unroll
        for (int off = 16; off > 0; off >>= 1) {
            const ull ob = __shfl_down_sync(0xffffffffu, best, off);
            const int op = __shfl_down_sync(0xffffffffu, bpos, off);
            if (ob < best) { best = ob; bpos = op; }
        }
        bpos = __shfl_sync(0xffffffffu, bpos, 0);
        if (lane == 0) g_knn_idx[q * KNN_K + sel] = (int)(wbuf[bpos] & 0xffffffffu);
        if (lane == (bpos & 31)) wbuf[bpos] = ~0ull;
        __syncwarp();
    }
}

// One block per query. blockDim = (64, 4). Thread y owns neighbors 4y..4y+3:
// one int4 idx load -> 4 independent gathers (MLP=4), cur reused from regs.
__global__ void __launch_bounds__(256) gather_kernel(
        const float4* __restrict__ feat_prev,
        const float4* __restrict__ feat_cur,
        float4* __restrict__ out) {
    const int q  = blockIdx.x;
    const int c4 = threadIdx.x;   // 0..63
    const int y  = threadIdx.y;   // 0..3

    const float4 cur = feat_cur[q * C4 + c4];
    const int4 iv = __ldg((const int4*)(g_knn_idx + q * KNN_K + 4 * y));

    const float4 p0 = feat_prev[iv.x * C4 + c4];
    const float4 p1 = feat_prev[iv.y * C4 + c4];
    const float4 p2 = feat_prev[iv.z * C4 + c4];
    const float4 p3 = feat_prev[iv.w * C4 + c4];

    const int row0 = q * KNN_K + 4 * y;
#pragma unroll
    for (int jj = 0; jj < 4; ++jj) {
        const float4 p = (jj == 0) ? p0 : (jj == 1) ? p1 : (jj == 2) ? p2 : p3;
        float4 dv;
        dv.x = p.x - cur.x; dv.y = p.y - cur.y;
        dv.z = p.z - cur.z; dv.w = p.w - cur.w;
        const long long row = row0 + jj;
        __stcs(&out[row * 128 + c4], dv);
        __stcs(&out[row * 128 + C4 + c4], cur);
    }
}

extern "C" void kernel_launch(void* const* d_in, const int* in_sizes, int n_in,
                              void* d_out, int out_size) {
    const float*  xyz_prev  = (const float*)d_in[0];
    const float*  xyz_cur   = (const float*)d_in[1];
    const float4* feat_prev = (const float4*)d_in[2];
    const float4* feat_cur  = (const float4*)d_in[3];
    float4* out = (float4*)d_out;

    (void)in_sizes; (void)n_in; (void)out_size;

    const int smem = WPB * BUF_CAP * sizeof(ull);   // 56 KB
    cudaFuncSetAttribute(knn_kernel, cudaFuncAttributeMaxDynamicSharedMemorySize, smem);

    bin_kernel<<<1, 1024>>>(xyz_prev);
    knn_kernel<<<KNN_BLOCKS, KNN_THREADS, smem>>>(xyz_cur);
    gather_kernel<<<NQ, dim3(64, 4)>>>(feat_prev, feat_cur, out);
}